// round 10
// baseline (speedup 1.0000x reference)
#include <cuda_runtime.h>
#include <cuda_fp16.h>

#define NMAX 10000
#define H1 4
#define C 128
#define F1 512
#define ELLW 256   // ELL storage width (Poisson(32) graph: max deg ~60)
#define GCAP 128   // gat2 smem cache width per chunk

// ---------------- scratch (static __device__) ----------------
__device__ int      g_is64;
__device__ int      g_cur[NMAX];
__device__ int      g_ell[NMAX * ELLW];
__device__ float    g_c[16];             // cs0[4], cs1[4], cd0[4], cd1[4]
__device__ __align__(16) float g_a0[NMAX * 4];
__device__ __align__(16) float g_a1[NMAX * 4];
__device__ __align__(16) __half2 g_h2h[NMAX * (C / 2)];
__device__ float g_as2[NMAX];
__device__ float g_ad2[NMAX];

__device__ __forceinline__ float lrelu(float v) { return v > 0.f ? v : 0.2f * v; }

// ---- packed f32x2 helpers ----
__device__ __forceinline__ unsigned long long pack_f2(float lo, float hi) {
    unsigned long long r;
    asm("mov.b64 %0, {%1, %2};" : "=l"(r) : "f"(lo), "f"(hi));
    return r;
}
__device__ __forceinline__ void fma_f32x2(unsigned long long& d,
                                          unsigned long long a, unsigned long long b) {
    asm("fma.rn.f32x2 %0, %1, %2, %3;" : "=l"(d) : "l"(a), "l"(b), "l"(d));
}
__device__ __forceinline__ float2 unpack_f2(unsigned long long v) {
    float lo, hi;
    asm("mov.b64 {%0, %1}, %2;" : "=f"(lo), "=f"(hi) : "l"(v));
    return make_float2(lo, hi);
}

// ---------------- setup: ELL init + rank-2 constants + dtype detect ----------------
__global__ void setup_kernel(const int* __restrict__ ei32, const float* __restrict__ W1,
                             const float* __restrict__ asw, const float* __restrict__ adw,
                             int n) {
    int i = blockIdx.x * blockDim.x + threadIdx.x;
    if (i < n) {
        g_cur[i] = 1;
        g_ell[i * ELLW] = i;             // self loop in slot 0
    }
    if (blockIdx.x == 0) {
        int t = threadIdx.x;
        if (t < 128) {
            int h = t >> 5, lane = t & 31;
            float cs0 = 0.f, cs1 = 0.f, cd0 = 0.f, cd1 = 0.f;
#pragma unroll
            for (int q = 0; q < 4; q++) {
                int f = h * C + lane + 32 * q;
                float w0 = W1[f], w1 = W1[F1 + f];
                float as = asw[f], ad = adw[f];
                cs0 += w0 * as; cs1 += w1 * as;
                cd0 += w0 * ad; cd1 += w1 * ad;
            }
#pragma unroll
            for (int o = 16; o > 0; o >>= 1) {
                cs0 += __shfl_down_sync(0xFFFFFFFFu, cs0, o);
                cs1 += __shfl_down_sync(0xFFFFFFFFu, cs1, o);
                cd0 += __shfl_down_sync(0xFFFFFFFFu, cd0, o);
                cd1 += __shfl_down_sync(0xFFFFFFFFu, cd1, o);
            }
            if (lane == 0) {
                g_c[h] = cs0; g_c[4 + h] = cs1; g_c[8 + h] = cd0; g_c[12 + h] = cd1;
            }
        } else if (t == 128) {
            int allzero = 1;
            for (int k = 1; k < 128; k += 2)
                if (ei32[k] != 0) { allzero = 0; break; }
            g_is64 = allzero;
        }
    }
}

// ---------------- scatter: 4 edges per thread ----------------
__global__ void scatter_kernel(const int* __restrict__ ei32, int e) {
    int i0 = (blockIdx.x * blockDim.x + threadIdx.x) * 4;
    if (i0 >= e) return;
    int cnt = min(4, e - i0);
    int src[4], dst[4];
    if (g_is64) {
        const long long* e64 = (const long long*)ei32;
#pragma unroll
        for (int k = 0; k < 4; k++)
            if (k < cnt) { src[k] = (int)e64[i0 + k]; dst[k] = (int)e64[e + i0 + k]; }
    } else {
#pragma unroll
        for (int k = 0; k < 4; k++)
            if (k < cnt) { src[k] = ei32[i0 + k]; dst[k] = ei32[e + i0 + k]; }
    }
#pragma unroll
    for (int k = 0; k < 4; k++) {
        if (k < cnt) {
            int pos = atomicAdd(&g_cur[dst[k]], 1);
            if (pos < ELLW) g_ell[dst[k] * ELLW + pos] = src[k];
        }
    }
}

// ---------------- layer 1: 8-lanes-per-node rank-2 GAT (no max shift) ----------------
__global__ void __launch_bounds__(256) gat1_kernel(const float* __restrict__ x, int n) {
    __shared__ float cs[16];
    int tid = threadIdx.x;
    if (tid < 16) cs[tid] = g_c[tid];
    __syncthreads();
    int w = tid >> 5, lane = tid & 31;
    int oct = lane >> 3, ol = lane & 7;
    int node = blockIdx.x * 32 + w * 4 + oct;   // 32 nodes per block
    bool valid = node < n;

    int deg = 0;
    const int* row = g_ell;
    float xd0 = 0.f, xd1 = 0.f;
    if (valid) {
        deg = min(g_cur[node], ELLW);
        row = g_ell + node * ELLW;
        float2 xv = *reinterpret_cast<const float2*>(x + 2 * node);
        xd0 = xv.x; xd1 = xv.y;
    }
    float dh[H1];
#pragma unroll
    for (int h = 0; h < H1; h++) dh[h] = xd0 * cs[8 + h] + xd1 * cs[12 + h];

    float sp[H1] = {0.f, 0.f, 0.f, 0.f};
    float s0[H1] = {0.f, 0.f, 0.f, 0.f};
    float s1[H1] = {0.f, 0.f, 0.f, 0.f};
    for (int j = ol; j < deg; j += 8) {
        int src = row[j];
        float2 xs = *reinterpret_cast<const float2*>(x + 2 * src);
#pragma unroll
        for (int h = 0; h < H1; h++) {
            float e = lrelu(fmaf(xs.x, cs[h], fmaf(xs.y, cs[4 + h], dh[h])));
            float p = __expf(e);
            sp[h] += p;
            s0[h] += p * xs.x;
            s1[h] += p * xs.y;
        }
    }
    // width-8 reduction within each octet
#pragma unroll
    for (int o = 4; o > 0; o >>= 1) {
#pragma unroll
        for (int h = 0; h < H1; h++) {
            sp[h] += __shfl_down_sync(0xFFFFFFFFu, sp[h], o, 8);
            s0[h] += __shfl_down_sync(0xFFFFFFFFu, s0[h], o, 8);
            s1[h] += __shfl_down_sync(0xFFFFFFFFu, s1[h], o, 8);
        }
    }
    if (ol == 0 && valid) {
        float4 a0, a1;
        float i0 = 1.f / (sp[0] + 1e-16f);
        float i1 = 1.f / (sp[1] + 1e-16f);
        float i2 = 1.f / (sp[2] + 1e-16f);
        float i3 = 1.f / (sp[3] + 1e-16f);
        a0.x = s0[0] * i0; a0.y = s0[1] * i1; a0.z = s0[2] * i2; a0.w = s0[3] * i3;
        a1.x = s1[0] * i0; a1.y = s1[1] * i1; a1.z = s1[2] * i2; a1.w = s1[3] * i3;
        ((float4*)g_a0)[node] = a0;
        ((float4*)g_a1)[node] = a1;
    }
}

// ---------------- layer 2 GEMM + fused out1 reconstruction + attn2 dots ----------------
__global__ void __launch_bounds__(256) gemm2_kernel(const float* __restrict__ W2,
                             const float* __restrict__ asw, const float* __restrict__ adw,
                             const float* __restrict__ W1, const float* __restrict__ b1,
                             int n) {
    const int NB = 16;
    int tid = threadIdx.x;
    int grp = tid >> 7;
    int t = tid & 127;
    int base = blockIdx.x * NB;
    __shared__ float4 sh[NB * 128];
    __shared__ float  sacc[NB * 128];
    __shared__ float  s_as[4][NB], s_ad[4][NB];

    const float4* W1_4 = (const float4*)W1;
    const float4* b1_4 = (const float4*)b1;

    for (int idx = tid; idx < NB * 128; idx += 256) {
        int m = idx >> 7, kq = idx & 127;
        int node = base + m;
        float4 v = make_float4(0.f, 0.f, 0.f, 0.f);
        if (node < n) {
            int h = kq >> 5;
            float A0 = g_a0[node * 4 + h];
            float A1 = g_a1[node * 4 + h];
            float4 w0 = W1_4[kq];
            float4 w1 = W1_4[128 + kq];
            float4 bb = b1_4[kq];
            v.x = fmaxf(fmaf(A0, w0.x, fmaf(A1, w1.x, bb.x)), 0.f);
            v.y = fmaxf(fmaf(A0, w0.y, fmaf(A1, w1.y, bb.y)), 0.f);
            v.z = fmaxf(fmaf(A0, w0.z, fmaf(A1, w1.z, bb.z)), 0.f);
            v.w = fmaxf(fmaf(A0, w0.w, fmaf(A1, w1.w, bb.w)), 0.f);
        }
        sh[idx] = v;
    }
    __syncthreads();

    const ulonglong2* shp = (const ulonglong2*)sh;
    unsigned long long acc2[NB];
#pragma unroll
    for (int m = 0; m < NB; m++) acc2[m] = pack_f2(0.f, 0.f);
    int kq0 = grp * 64;
    for (int kk = 0; kk < 64; kk++) {
        int kq = kq0 + kk;
        int k = kq * 4;
        unsigned long long wp01 = pack_f2(W2[(k + 0) * C + t], W2[(k + 1) * C + t]);
        unsigned long long wp23 = pack_f2(W2[(k + 2) * C + t], W2[(k + 3) * C + t]);
#pragma unroll
        for (int m = 0; m < NB; m++) {
            ulonglong2 sv = shp[m * 128 + kq];
            fma_f32x2(acc2[m], sv.x, wp01);
            fma_f32x2(acc2[m], sv.y, wp23);
        }
    }
    if (grp == 1) {
#pragma unroll
        for (int m = 0; m < NB; m++) {
            float2 pr = unpack_f2(acc2[m]);
            sacc[m * 128 + t] = pr.x + pr.y;
        }
    }
    __syncthreads();
    if (grp == 0) {
        float a_s = asw[t], a_d = adw[t];
        int w = t >> 5, lane = t & 31;
#pragma unroll
        for (int m = 0; m < NB; m++) {
            float2 pr = unpack_f2(acc2[m]);
            float hv = pr.x + pr.y + sacc[m * 128 + t];
            sacc[m * 128 + t] = hv;
            float vs = hv * a_s, vd = hv * a_d;
#pragma unroll
            for (int o = 16; o > 0; o >>= 1) {
                vs += __shfl_down_sync(0xFFFFFFFFu, vs, o);
                vd += __shfl_down_sync(0xFFFFFFFFu, vd, o);
            }
            if (lane == 0) { s_as[w][m] = vs; s_ad[w][m] = vd; }
        }
    }
    __syncthreads();
    if (tid < NB) {
        int node = base + tid;
        if (node < n) {
            g_as2[node] = s_as[0][tid] + s_as[1][tid] + s_as[2][tid] + s_as[3][tid];
            g_ad2[node] = s_ad[0][tid] + s_ad[1][tid] + s_ad[2][tid] + s_ad[3][tid];
        }
    }
    for (int idx = tid; idx < NB * 64; idx += 256) {
        int m = idx >> 6, p = idx & 63;
        int node = base + m;
        if (node < n) {
            __half2 hp = __floats2half2_rn(sacc[m * 128 + 2 * p], sacc[m * 128 + 2 * p + 1]);
            g_h2h[node * 64 + p] = hp;
        }
    }
}

// ---------------- layer 2: warp-per-node softmax (no shift) + fp16 aggregation ----------------
__global__ void __launch_bounds__(256) gat2_kernel(const float* __restrict__ b2,
                            const float* __restrict__ Wp, const float* __restrict__ bp,
                            float* __restrict__ out, int n) {
    __shared__ float s_p[8][GCAP];
    __shared__ int   s_src[8][GCAP];
    int tid = threadIdx.x;
    int w = tid >> 5, lane = tid & 31;
    int node = blockIdx.x * 8 + w;
    if (node >= n) return;

    int deg = min(g_cur[node], ELLW);
    const int* row = g_ell + node * ELLW;
    float ad = g_ad2[node];

    float4 acc = make_float4(0.f, 0.f, 0.f, 0.f);
    float psum = 0.f;
    for (int base = 0; base < deg; base += GCAP) {
        int cnt = min(GCAP, deg - base);
        for (int j = lane; j < cnt; j += 32) {
            int src = row[base + j];
            s_src[w][j] = src;
            float p = __expf(lrelu(g_as2[src] + ad));
            s_p[w][j] = p;
            psum += p;
        }
        __syncwarp();
#pragma unroll 4
        for (int j = 0; j < cnt; j++) {
            int src = s_src[w][j];
            float pj = s_p[w][j];
            uint2 raw = *reinterpret_cast<const uint2*>(&g_h2h[src * 64 + 2 * lane]);
            float2 fa = __half22float2(*reinterpret_cast<__half2*>(&raw.x));
            float2 fb = __half22float2(*reinterpret_cast<__half2*>(&raw.y));
            acc.x += pj * fa.x; acc.y += pj * fa.y;
            acc.z += pj * fb.x; acc.w += pj * fb.y;
        }
        __syncwarp();
    }
#pragma unroll
    for (int o = 16; o > 0; o >>= 1)
        psum += __shfl_xor_sync(0xFFFFFFFFu, psum, o);

    float inv = 1.f / (psum + 1e-16f);
    float4 bq = ((const float4*)b2)[lane];
    float4 wq = ((const float4*)Wp)[lane];
    float o0 = fmaxf(acc.x * inv + bq.x, 0.f);
    float o1 = fmaxf(acc.y * inv + bq.y, 0.f);
    float o2 = fmaxf(acc.z * inv + bq.z, 0.f);
    float o3 = fmaxf(acc.w * inv + bq.w, 0.f);
    float v = o0 * wq.x + o1 * wq.y + o2 * wq.z + o3 * wq.w;
#pragma unroll
    for (int o = 16; o > 0; o >>= 1)
        v += __shfl_down_sync(0xFFFFFFFFu, v, o);
    if (lane == 0) out[node] = v + bp[0];
}

// ---------------- launch ----------------
extern "C" void kernel_launch(void* const* d_in, const int* in_sizes, int n_in,
                              void* d_out, int out_size) {
    const float* x    = (const float*)d_in[0];
    const int*   ei32 = (const int*)d_in[1];
    const float* W1   = (const float*)d_in[2];
    const float* as1w = (const float*)d_in[3];
    const float* ad1w = (const float*)d_in[4];
    const float* b1   = (const float*)d_in[5];
    const float* W2   = (const float*)d_in[6];
    const float* as2w = (const float*)d_in[7];
    const float* ad2w = (const float*)d_in[8];
    const float* b2   = (const float*)d_in[9];
    const float* Wp   = (const float*)d_in[10];
    const float* bp   = (const float*)d_in[11];
    float* out = (float*)d_out;

    int n = in_sizes[0] / 2;   // x is [N,2]
    int e = in_sizes[1] / 2;   // edge_index is [2,E]

    setup_kernel<<<(n + 255) / 256, 256>>>(ei32, W1, as1w, ad1w, n);
    scatter_kernel<<<(e + 1023) / 1024, 256>>>(ei32, e);

    gat1_kernel<<<(n + 31) / 32, 256>>>(x, n);
    gemm2_kernel<<<(n + 15) / 16, 256>>>(W2, as2w, ad2w, W1, b1, n);
    gat2_kernel<<<(n + 7) / 8, 256>>>(b2, Wp, bp, out, n);
}

// round 12
// speedup vs baseline: 1.5663x; 1.5663x over previous
#include <cuda_runtime.h>
#include <cuda_fp16.h>
#include <cstdint>

#define NMAX 10000
#define H1 4
#define C 128
#define F1 512
#define ELLW 256
#define GCAP 128
#define MTILE 128
#define KCH 64          // K chunk
#define BPAD 72         // padded row stride in halves (64+8)

// ---------------- scratch ----------------
__device__ int      g_is64;
__device__ int      g_cur[NMAX];
__device__ int      g_ell[NMAX * ELLW];
__device__ float    g_c[16];
__device__ __align__(16) float g_a0[NMAX * 4];
__device__ __align__(16) float g_a1[NMAX * 4];
__device__ __align__(16) __half2 g_h2h[NMAX * (C / 2)];
__device__ float g_as2[NMAX];
__device__ float g_ad2[NMAX];

__device__ __forceinline__ float lrelu(float v) { return v > 0.f ? v : 0.2f * v; }

// ---------------- setup: ELL init + rank-2 constants + dtype detect ----------------
__global__ void setup_kernel(const int* __restrict__ ei32, const float* __restrict__ W1,
                             const float* __restrict__ asw, const float* __restrict__ adw,
                             int n) {
    int i = blockIdx.x * blockDim.x + threadIdx.x;
    if (i < n) {
        g_cur[i] = 1;
        g_ell[i * ELLW] = i;
    }
    if (blockIdx.x == 0) {
        int t = threadIdx.x;
        if (t < 128) {
            int h = t >> 5, lane = t & 31;
            float cs0 = 0.f, cs1 = 0.f, cd0 = 0.f, cd1 = 0.f;
#pragma unroll
            for (int q = 0; q < 4; q++) {
                int f = h * C + lane + 32 * q;
                float w0 = W1[f], w1 = W1[F1 + f];
                float as = asw[f], ad = adw[f];
                cs0 += w0 * as; cs1 += w1 * as;
                cd0 += w0 * ad; cd1 += w1 * ad;
            }
#pragma unroll
            for (int o = 16; o > 0; o >>= 1) {
                cs0 += __shfl_down_sync(0xFFFFFFFFu, cs0, o);
                cs1 += __shfl_down_sync(0xFFFFFFFFu, cs1, o);
                cd0 += __shfl_down_sync(0xFFFFFFFFu, cd0, o);
                cd1 += __shfl_down_sync(0xFFFFFFFFu, cd1, o);
            }
            if (lane == 0) {
                g_c[h] = cs0; g_c[4 + h] = cs1; g_c[8 + h] = cd0; g_c[12 + h] = cd1;
            }
        } else if (t == 128) {
            int allzero = 1;
            for (int k = 1; k < 128; k += 2)
                if (ei32[k] != 0) { allzero = 0; break; }
            g_is64 = allzero;
        }
    }
}

// ---------------- scatter: 4 edges per thread ----------------
__global__ void scatter_kernel(const int* __restrict__ ei32, int e) {
    int i0 = (blockIdx.x * blockDim.x + threadIdx.x) * 4;
    if (i0 >= e) return;
    int cnt = min(4, e - i0);
    int src[4], dst[4];
    if (g_is64) {
        const long long* e64 = (const long long*)ei32;
#pragma unroll
        for (int k = 0; k < 4; k++)
            if (k < cnt) { src[k] = (int)e64[i0 + k]; dst[k] = (int)e64[e + i0 + k]; }
    } else {
#pragma unroll
        for (int k = 0; k < 4; k++)
            if (k < cnt) { src[k] = ei32[i0 + k]; dst[k] = ei32[e + i0 + k]; }
    }
#pragma unroll
    for (int k = 0; k < 4; k++) {
        if (k < cnt) {
            int pos = atomicAdd(&g_cur[dst[k]], 1);
            if (pos < ELLW) g_ell[dst[k] * ELLW + pos] = src[k];
        }
    }
}

// ---------------- layer 1: 8-lanes-per-node rank-2 GAT ----------------
__global__ void __launch_bounds__(256) gat1_kernel(const float* __restrict__ x, int n) {
    __shared__ float cs[16];
    int tid = threadIdx.x;
    if (tid < 16) cs[tid] = g_c[tid];
    __syncthreads();
    int w = tid >> 5, lane = tid & 31;
    int oct = lane >> 3, ol = lane & 7;
    int node = blockIdx.x * 32 + w * 4 + oct;
    bool valid = node < n;

    int deg = 0;
    const int* row = g_ell;
    float xd0 = 0.f, xd1 = 0.f;
    if (valid) {
        deg = min(g_cur[node], ELLW);
        row = g_ell + node * ELLW;
        float2 xv = *reinterpret_cast<const float2*>(x + 2 * node);
        xd0 = xv.x; xd1 = xv.y;
    }
    float dh[H1];
#pragma unroll
    for (int h = 0; h < H1; h++) dh[h] = xd0 * cs[8 + h] + xd1 * cs[12 + h];

    float sp[H1] = {0.f, 0.f, 0.f, 0.f};
    float s0[H1] = {0.f, 0.f, 0.f, 0.f};
    float s1[H1] = {0.f, 0.f, 0.f, 0.f};
    for (int j = ol; j < deg; j += 8) {
        int src = row[j];
        float2 xs = *reinterpret_cast<const float2*>(x + 2 * src);
#pragma unroll
        for (int h = 0; h < H1; h++) {
            float e = lrelu(fmaf(xs.x, cs[h], fmaf(xs.y, cs[4 + h], dh[h])));
            float p = __expf(e);
            sp[h] += p;
            s0[h] += p * xs.x;
            s1[h] += p * xs.y;
        }
    }
#pragma unroll
    for (int o = 4; o > 0; o >>= 1) {
#pragma unroll
        for (int h = 0; h < H1; h++) {
            sp[h] += __shfl_down_sync(0xFFFFFFFFu, sp[h], o, 8);
            s0[h] += __shfl_down_sync(0xFFFFFFFFu, s0[h], o, 8);
            s1[h] += __shfl_down_sync(0xFFFFFFFFu, s1[h], o, 8);
        }
    }
    if (ol == 0 && valid) {
        float4 a0, a1;
        float i0 = 1.f / (sp[0] + 1e-16f);
        float i1 = 1.f / (sp[1] + 1e-16f);
        float i2 = 1.f / (sp[2] + 1e-16f);
        float i3 = 1.f / (sp[3] + 1e-16f);
        a0.x = s0[0] * i0; a0.y = s0[1] * i1; a0.z = s0[2] * i2; a0.w = s0[3] * i3;
        a1.x = s1[0] * i0; a1.y = s1[1] * i1; a1.z = s1[2] * i2; a1.w = s1[3] * i3;
        ((float4*)g_a0)[node] = a0;
        ((float4*)g_a1)[node] = a1;
    }
}

// ---------------- layer 2 GEMM: mma.sync m16n8k16 f16, M=128 N=128 K=512 ----------------
__global__ void __launch_bounds__(256) gemm2_mma(const float* __restrict__ W2,
                            const float* __restrict__ asw, const float* __restrict__ adw,
                            const float* __restrict__ W1, const float* __restrict__ b1,
                            int n) {
    __shared__ __half As[MTILE * BPAD];      // 18432 B  (out1 tile, m-major)
    __shared__ __half Bs[C * BPAD];          // 18432 B  (W2^T tile, n-major)
    __shared__ float w0s[KCH], w1s[KCH], b1s[KCH];
    __shared__ float asw_s[C], adw_s[C];

    int tid = threadIdx.x;
    int w = tid >> 5, lane = tid & 31;
    int g = lane >> 2, tg = lane & 3;
    int base = blockIdx.x * MTILE;

    if (tid < C) { asw_s[tid] = asw[tid]; adw_s[tid] = adw[tid]; }

    float c[16][4];
#pragma unroll
    for (int nt = 0; nt < 16; nt++) {
        c[nt][0] = 0.f; c[nt][1] = 0.f; c[nt][2] = 0.f; c[nt][3] = 0.f;
    }

    for (int chunk = 0; chunk < 8; chunk++) {
        int k0g = chunk * KCH;               // global k offset
        int head = chunk >> 1;               // 64-chunks align within 128-wide heads
        if (tid < KCH) {
            w0s[tid] = W1[k0g + tid];
            w1s[tid] = W1[F1 + k0g + tid];
            b1s[tid] = b1[k0g + tid];
        }
        __syncthreads();
        // stage A: out1[m][k] = relu(A0*W1[0][k] + A1*W1[1][k] + b1[k]), fp16
        for (int idx = tid; idx < MTILE * 32; idx += 256) {
            int m = idx >> 5, kp = idx & 31;
            int node = base + m;
            float A0 = 0.f, A1 = 0.f;
            if (node < n) {
                A0 = g_a0[node * 4 + head];
                A1 = g_a1[node * 4 + head];
            }
            float v0 = fmaxf(fmaf(A0, w0s[2 * kp],     fmaf(A1, w1s[2 * kp],     b1s[2 * kp])),     0.f);
            float v1 = fmaxf(fmaf(A0, w0s[2 * kp + 1], fmaf(A1, w1s[2 * kp + 1], b1s[2 * kp + 1])), 0.f);
            *reinterpret_cast<__half2*>(&As[m * BPAD + 2 * kp]) = __floats2half2_rn(v0, v1);
        }
        // stage B: Bs[ch][k] = W2[k0g+k][ch], fp16 (n-major for col fragment)
        {
            int ch = tid & 127;
            for (int kp = (tid >> 7); kp < 32; kp += 2) {
                float v0 = W2[(k0g + 2 * kp) * C + ch];
                float v1 = W2[(k0g + 2 * kp + 1) * C + ch];
                *reinterpret_cast<__half2*>(&Bs[ch * BPAD + 2 * kp]) = __floats2half2_rn(v0, v1);
            }
        }
        __syncthreads();
        // compute: 4 ksteps of 16
#pragma unroll
        for (int ks = 0; ks < 4; ks++) {
            int k0 = ks * 16;
            uint32_t a0 = *reinterpret_cast<const uint32_t*>(&As[(w * 16 + g)     * BPAD + k0 + 2 * tg]);
            uint32_t a1 = *reinterpret_cast<const uint32_t*>(&As[(w * 16 + 8 + g) * BPAD + k0 + 2 * tg]);
            uint32_t a2 = *reinterpret_cast<const uint32_t*>(&As[(w * 16 + g)     * BPAD + k0 + 2 * tg + 8]);
            uint32_t a3 = *reinterpret_cast<const uint32_t*>(&As[(w * 16 + 8 + g) * BPAD + k0 + 2 * tg + 8]);
#pragma unroll
            for (int nt = 0; nt < 16; nt++) {
                uint32_t b0 = *reinterpret_cast<const uint32_t*>(&Bs[(nt * 8 + g) * BPAD + k0 + 2 * tg]);
                uint32_t b1r = *reinterpret_cast<const uint32_t*>(&Bs[(nt * 8 + g) * BPAD + k0 + 2 * tg + 8]);
                asm volatile(
                    "mma.sync.aligned.m16n8k16.row.col.f32.f16.f16.f32 "
                    "{%0,%1,%2,%3}, {%4,%5,%6,%7}, {%8,%9}, {%0,%1,%2,%3};"
                    : "+f"(c[nt][0]), "+f"(c[nt][1]), "+f"(c[nt][2]), "+f"(c[nt][3])
                    : "r"(a0), "r"(a1), "r"(a2), "r"(a3), "r"(b0), "r"(b1r));
            }
        }
        __syncthreads();
    }

    // epilogue: rows r1 = base+16w+g (c0,c1), r2 = r1+8 (c2,c3)
    int r1 = base + w * 16 + g;
    int r2 = r1 + 8;
    float as1v = 0.f, ad1v = 0.f, as2v = 0.f, ad2v = 0.f;
#pragma unroll
    for (int nt = 0; nt < 16; nt++) {
        int col = nt * 8 + 2 * tg;
        float ws0 = asw_s[col], ws1 = asw_s[col + 1];
        float wd0 = adw_s[col], wd1 = adw_s[col + 1];
        as1v += c[nt][0] * ws0 + c[nt][1] * ws1;
        ad1v += c[nt][0] * wd0 + c[nt][1] * wd1;
        as2v += c[nt][2] * ws0 + c[nt][3] * ws1;
        ad2v += c[nt][2] * wd0 + c[nt][3] * wd1;
        __half2 p1 = __floats2half2_rn(c[nt][0], c[nt][1]);
        __half2 p2 = __floats2half2_rn(c[nt][2], c[nt][3]);
        if (r1 < n) g_h2h[r1 * 64 + nt * 4 + tg] = p1;
        if (r2 < n) g_h2h[r2 * 64 + nt * 4 + tg] = p2;
    }
#pragma unroll
    for (int o = 1; o < 4; o <<= 1) {
        as1v += __shfl_down_sync(0xFFFFFFFFu, as1v, o, 4);
        ad1v += __shfl_down_sync(0xFFFFFFFFu, ad1v, o, 4);
        as2v += __shfl_down_sync(0xFFFFFFFFu, as2v, o, 4);
        ad2v += __shfl_down_sync(0xFFFFFFFFu, ad2v, o, 4);
    }
    if (tg == 0) {
        if (r1 < n) { g_as2[r1] = as1v; g_ad2[r1] = ad1v; }
        if (r2 < n) { g_as2[r2] = as2v; g_ad2[r2] = ad2v; }
    }
}

// ---------------- layer 2: warp-per-node softmax + fp16 aggregation ----------------
__global__ void __launch_bounds__(256) gat2_kernel(const float* __restrict__ b2,
                            const float* __restrict__ Wp, const float* __restrict__ bp,
                            float* __restrict__ out, int n) {
    __shared__ float s_p[8][GCAP];
    __shared__ int   s_src[8][GCAP];
    int tid = threadIdx.x;
    int w = tid >> 5, lane = tid & 31;
    int node = blockIdx.x * 8 + w;
    if (node >= n) return;

    int deg = min(g_cur[node], ELLW);
    const int* row = g_ell + node * ELLW;
    float ad = g_ad2[node];

    float4 acc = make_float4(0.f, 0.f, 0.f, 0.f);
    float psum = 0.f;
    for (int base = 0; base < deg; base += GCAP) {
        int cnt = min(GCAP, deg - base);
        for (int j = lane; j < cnt; j += 32) {
            int src = row[base + j];
            s_src[w][j] = src;
            float p = __expf(lrelu(g_as2[src] + ad));
            s_p[w][j] = p;
            psum += p;
        }
        __syncwarp();
#pragma unroll 4
        for (int j = 0; j < cnt; j++) {
            int src = s_src[w][j];
            float pj = s_p[w][j];
            uint2 raw = *reinterpret_cast<const uint2*>(&g_h2h[src * 64 + 2 * lane]);
            float2 fa = __half22float2(*reinterpret_cast<__half2*>(&raw.x));
            float2 fb = __half22float2(*reinterpret_cast<__half2*>(&raw.y));
            acc.x += pj * fa.x; acc.y += pj * fa.y;
            acc.z += pj * fb.x; acc.w += pj * fb.y;
        }
        __syncwarp();
    }
#pragma unroll
    for (int o = 16; o > 0; o >>= 1)
        psum += __shfl_xor_sync(0xFFFFFFFFu, psum, o);

    float inv = 1.f / (psum + 1e-16f);
    float4 bq = ((const float4*)b2)[lane];
    float4 wq = ((const float4*)Wp)[lane];
    float o0 = fmaxf(acc.x * inv + bq.x, 0.f);
    float o1 = fmaxf(acc.y * inv + bq.y, 0.f);
    float o2 = fmaxf(acc.z * inv + bq.z, 0.f);
    float o3 = fmaxf(acc.w * inv + bq.w, 0.f);
    float v = o0 * wq.x + o1 * wq.y + o2 * wq.z + o3 * wq.w;
#pragma unroll
    for (int o = 16; o > 0; o >>= 1)
        v += __shfl_down_sync(0xFFFFFFFFu, v, o);
    if (lane == 0) out[node] = v + bp[0];
}

// ---------------- launch ----------------
extern "C" void kernel_launch(void* const* d_in, const int* in_sizes, int n_in,
                              void* d_out, int out_size) {
    const float* x    = (const float*)d_in[0];
    const int*   ei32 = (const int*)d_in[1];
    const float* W1   = (const float*)d_in[2];
    const float* as1w = (const float*)d_in[3];
    const float* ad1w = (const float*)d_in[4];
    const float* b1   = (const float*)d_in[5];
    const float* W2   = (const float*)d_in[6];
    const float* as2w = (const float*)d_in[7];
    const float* ad2w = (const float*)d_in[8];
    const float* b2   = (const float*)d_in[9];
    const float* Wp   = (const float*)d_in[10];
    const float* bp   = (const float*)d_in[11];
    float* out = (float*)d_out;

    int n = in_sizes[0] / 2;
    int e = in_sizes[1] / 2;

    setup_kernel<<<(n + 255) / 256, 256>>>(ei32, W1, as1w, ad1w, n);
    scatter_kernel<<<(e + 1023) / 1024, 256>>>(ei32, e);

    gat1_kernel<<<(n + 31) / 32, 256>>>(x, n);
    gemm2_mma<<<(n + MTILE - 1) / MTILE, 256>>>(W2, as2w, ad2w, W1, b1, n);
    gat2_kernel<<<(n + 7) / 8, 256>>>(b2, Wp, bp, out, n);
}